// round 15
// baseline (speedup 1.0000x reference)
#include <cuda_runtime.h>
#include <cuda_bf16.h>
#include <cstdint>

// CrossPatchModule closed form:
//   B=4, C=64, H=W=512, PH=PW=8, PN=64, kh=kw=64
//   ph=h>>6, i=h&63, pw=w>>6, j=w&63
//   s = ph*8+pw;  m=(c+s)&63
//   out[b,c,h,w] = x[b,c, (m>>3)*64 + i, (m&7)*64 + j] + abs_pos[c*64+m]
//
// R14: MLP=5 at occupancy 8 (last untested frontier cell).
//   2048 thr/SM * 5 = 10240 in-flight loads (+25% over R1's 8192) while
//   keeping 8 CTAs/SM -- feasible iff regs <= 32 (R7 used 26).
//   Chunk 1280 can straddle images -> c/base computed per-k (R1-style,
//   measured tie with hoisted version). Tail (256 float4) handled by one
//   dedicated block so the 13107 full blocks stay unpredicated.

#define N_F4    16777216u            // 4*64*512*512 / 4
#define CHUNK   1280u                // 256 threads * 5 float4
#define NFULL   13107u               // full blocks: 13107*1280 = 16776960
#define TAIL0   16776960u            // remaining 256 float4

__global__ __launch_bounds__(256, 8)
void crosspatch_kernel(const float4* __restrict__ x,
                       const float*  __restrict__ ap,
                       float4*       __restrict__ out)
{
    if (blockIdx.x < NFULL) {
        unsigned t0 = blockIdx.x * CHUNK + threadIdx.x;

        // bits 0..6 of t invariant under +k*256
        unsigned w4 = t0 & 127u;
        unsigned pw = w4 >> 4;
        unsigned j4 = w4 & 15u;

        unsigned src[5];
        float    add[5];

#pragma unroll
        for (int k = 0; k < 5; ++k) {
            unsigned t    = t0 + k * 256u;
            unsigned h    = (t >> 7) & 511u;
            unsigned c    = (t >> 16) & 63u;
            unsigned base = (t >> 16) << 16;   // image base (65536 float4)

            unsigned m  = (c + ((h >> 6) << 3) + pw) & 63u;
            unsigned i  = h & 63u;

            unsigned src_h  = ((m >> 3) << 6) | i;
            unsigned src_w4 = ((m & 7u) << 4) | j4;

            src[k] = base + (src_h << 7) + src_w4;
            add[k] = __ldg(&ap[(c << 6) | m]);
        }

        float4 v[5];
#pragma unroll
        for (int k = 0; k < 5; ++k)
            v[k] = __ldcs(&x[src[k]]);         // streaming gather, front-batched

#pragma unroll
        for (int k = 0; k < 5; ++k) {
            float a = add[k];
            v[k].x += a; v[k].y += a; v[k].z += a; v[k].w += a;
            __stcs(&out[t0 + k * 256u], v[k]); // sequential streaming write
        }
    } else {
        // Tail: 256 float4, one per thread.
        unsigned t  = TAIL0 + threadIdx.x;
        unsigned w4 = t & 127u;
        unsigned pw = w4 >> 4;
        unsigned j4 = w4 & 15u;
        unsigned h  = (t >> 7) & 511u;
        unsigned c  = (t >> 16) & 63u;
        unsigned base = (t >> 16) << 16;

        unsigned m  = (c + ((h >> 6) << 3) + pw) & 63u;
        unsigned i  = h & 63u;
        unsigned src_h  = ((m >> 3) << 6) | i;
        unsigned src_w4 = ((m & 7u) << 4) | j4;

        float4 v = __ldcs(&x[base + (src_h << 7) + src_w4]);
        float  a = __ldg(&ap[(c << 6) | m]);
        v.x += a; v.y += a; v.z += a; v.w += a;
        __stcs(&out[t], v);
    }
}

extern "C" void kernel_launch(void* const* d_in, const int* in_sizes, int n_in,
                              void* d_out, int out_size)
{
    const float4* x   = (const float4*)d_in[0];   // (4,64,512,512) fp32
    const float*  ap  = (const float*)d_in[1];    // (1,1,64,64,1,1) fp32
    float4*       out = (float4*)d_out;

    crosspatch_kernel<<<NFULL + 1, 256>>>(x, ap, out);
}

// round 16
// speedup vs baseline: 1.0027x; 1.0027x over previous
#include <cuda_runtime.h>
#include <cuda_bf16.h>
#include <cstdint>

// CrossPatchModule closed form:
//   B=4, C=64, H=W=512, PH=PW=8, PN=64, kh=kw=64
//   ph=h>>6, i=h&63, pw=w>>6, j=w&63
//   s = ph*8+pw;  m=(c+s)&63
//   out[b,c,h,w] = x[b,c, (m>>3)*64 + i, (m&7)*64 + j] + abs_pos[c*64+m]
//
// FINAL (R7 config): pure permutation gather + scalar add, 512MB irreducible
// traffic, HBM-bound at the measured mixed-R/W ceiling (~6.5 TB/s, DRAM 82%).
//   - write-linear / read-gather orientation (tie with scatter; best bench)
//   - MLP=4 per thread, front-batched (optimum of MLP 1/4/5/6/8 — R14's
//     MLP=5 at +25% in-flight and 85% occ changed nothing: DRAM saturated)
//   - streaming (.cs) hints, plain .128 width (L2::256B hint regressed)
//   - k-invariant index ALU hoisted; 26 regs, 8 CTAs/SM
// Persistent grids, occupancy trades, and prefetch hints all measured
// neutral-or-worse. This is the machine floor for this problem.

__global__ __launch_bounds__(256, 8)
void crosspatch_kernel(const float4* __restrict__ x,
                       const float*  __restrict__ ap,
                       float4*       __restrict__ out)
{
    // 4 float4 per thread at stride 256 float4: each warp access is 32
    // consecutive float4 (512B), fully coalesced on both sides.
    unsigned t0 = blockIdx.x * 1024u + threadIdx.x;

    // k-invariant pieces: t0 + k*256 leaves bits 0..6 unchanged, and a
    // 1024-float4 chunk never straddles an image (65536 % 1024 == 0),
    // so c and base are constant across the 4 elements.
    unsigned w4 = t0 & 127u;
    unsigned pw = w4 >> 4;
    unsigned j4 = w4 & 15u;
    unsigned c  = (t0 >> 16) & 63u;
    unsigned base = (t0 >> 16) << 16;          // ((b*64+c) image) * 65536

    unsigned src[4];
    float    add[4];

#pragma unroll
    for (int k = 0; k < 4; ++k) {
        unsigned h  = ((t0 + k * 256u) >> 7) & 511u;
        unsigned ph = h >> 6;
        unsigned i  = h & 63u;

        unsigned m  = (c + ph * 8u + pw) & 63u;
        unsigned src_h  = ((m >> 3) << 6) | i;
        unsigned src_w4 = ((m & 7u) << 4) | j4;

        src[k] = base + (src_h << 7) + src_w4;
        add[k] = __ldg(&ap[(c << 6) | m]);
    }

    float4 v[4];
#pragma unroll
    for (int k = 0; k < 4; ++k)
        v[k] = __ldcs(&x[src[k]]);             // streaming gather (no reuse)

#pragma unroll
    for (int k = 0; k < 4; ++k) {
        float a = add[k];
        v[k].x += a; v[k].y += a; v[k].z += a; v[k].w += a;
        __stcs(&out[t0 + k * 256u], v[k]);     // sequential streaming write
    }
}

extern "C" void kernel_launch(void* const* d_in, const int* in_sizes, int n_in,
                              void* d_out, int out_size)
{
    const float4* x   = (const float4*)d_in[0];   // (4,64,512,512) fp32
    const float*  ap  = (const float*)d_in[1];    // (1,1,64,64,1,1) fp32
    float4*       out = (float4*)d_out;

    crosspatch_kernel<<<16384, 256>>>(x, ap, out);
}